// round 1
// baseline (speedup 1.0000x reference)
#include <cuda_runtime.h>
#include <math.h>

#define S_LEN 32
#define T_LEN 32
#define BATCH 64
#define HID   512
#define BH    (BATCH * HID)        // 32768 floats per [B,H] slab
#define Z4    (BATCH * 4 * HID)    // 131072 floats per [B,4H] slab
#define MAXC  32                   // max cells on a diagonal

// ---------------- persistent device scratch (allocation-free rule) ----------
__device__ __align__(16) float g_s_x[S_LEN * BH];
__device__ __align__(16) float g_s_h[S_LEN * BH];
__device__ __align__(16) float g_s_m[S_LEN * BH];
__device__ __align__(16) float g_t_x[T_LEN * BH];
__device__ __align__(16) float g_t_h[T_LEN * BH];
__device__ __align__(16) float g_t_m[T_LEN * BH];
__device__ __align__(16) float g_hmid[MAXC * BH];      // per-cell hmid [64,512]
__device__ __align__(16) float g_r  [MAXC * Z4];       // hmid @ W_rec
__device__ __align__(16) float g_zs [MAXC * Z4];       // s_x  @ W_kernel
__device__ __align__(16) float g_zt [MAXC * Z4];       // t_x  @ W_kernel

// ---------------- 64x64 fp32 GEMM tile, 256 threads, BK=16 ------------------
// C[64, n0:n0+64] = A[64,K] @ W[K,N] (+bias). A row stride fixed at 512.
// A is optionally a K-concat of two [64,512] slabs (A0 then A1).
__device__ __forceinline__ void gemm64(
    const float* __restrict__ A0, const float* __restrict__ A1,
    int K, const float* __restrict__ W, int ldw,
    float* __restrict__ C, int ldc,
    const float* __restrict__ bias, int n0)
{
    __shared__ __align__(16) float As[16][64];
    __shared__ __align__(16) float Ws[16][64];

    const int tid = threadIdx.x;
    const int tx  = tid & 15;   // n group
    const int ty  = tid >> 4;   // m group

    float acc[4][4];
#pragma unroll
    for (int a = 0; a < 4; a++)
#pragma unroll
        for (int b = 0; b < 4; b++) acc[a][b] = 0.f;

    // A-tile load mapping: 64x16 tile, each thread one float4 along k
    const int la_m = (tid * 4) >> 4;      // 0..63
    const int la_k = (tid * 4) & 15;      // 0,4,8,12
    // W-tile load mapping: 16x64 tile, each thread one float4 along n
    const int lw_k = (tid * 4) >> 6;      // 0..15
    const int lw_n = (tid * 4) & 63;      // multiple of 4

    for (int k0 = 0; k0 < K; k0 += 16) {
        const float* Ab = (k0 < 512) ? (A0 + k0) : (A1 + (k0 - 512));
        {
            float4 v = *reinterpret_cast<const float4*>(Ab + la_m * 512 + la_k);
            As[la_k + 0][la_m] = v.x;
            As[la_k + 1][la_m] = v.y;
            As[la_k + 2][la_m] = v.z;
            As[la_k + 3][la_m] = v.w;
        }
        {
            float4 v = *reinterpret_cast<const float4*>(
                W + (size_t)(k0 + lw_k) * ldw + n0 + lw_n);
            *reinterpret_cast<float4*>(&Ws[lw_k][lw_n]) = v;
        }
        __syncthreads();

#pragma unroll
        for (int kk = 0; kk < 16; kk++) {
            float4 a4 = *reinterpret_cast<const float4*>(&As[kk][ty * 4]);
            float4 w4 = *reinterpret_cast<const float4*>(&Ws[kk][tx * 4]);
            float a[4] = {a4.x, a4.y, a4.z, a4.w};
            float w[4] = {w4.x, w4.y, w4.z, w4.w};
#pragma unroll
            for (int im = 0; im < 4; im++)
#pragma unroll
                for (int in = 0; in < 4; in++)
                    acc[im][in] += a[im] * w[in];
        }
        __syncthreads();
    }

    const int mBase = ty * 4;
    const int nBase = n0 + tx * 4;
    float b4[4] = {0.f, 0.f, 0.f, 0.f};
    if (bias) {
        float4 bv = *reinterpret_cast<const float4*>(bias + nBase);
        b4[0] = bv.x; b4[1] = bv.y; b4[2] = bv.z; b4[3] = bv.w;
    }
#pragma unroll
    for (int im = 0; im < 4; im++) {
        float4 o;
        o.x = acc[im][0] + b4[0];
        o.y = acc[im][1] + b4[1];
        o.z = acc[im][2] + b4[2];
        o.w = acc[im][3] + b4[3];
        *reinterpret_cast<float4*>(C + (size_t)(mBase + im) * ldc + nBase) = o;
    }
}

// ---------------- kernels ----------------------------------------------------
__global__ void k_init(const float* __restrict__ src, const float* __restrict__ tgt)
{
    int idx = blockIdx.x * blockDim.x + threadIdx.x;   // [0, S*B*H)
    g_s_x[idx] = src[idx];
    g_s_h[idx] = 0.f;
    g_s_m[idx] = 0.f;
    g_t_x[idx] = tgt[idx];
    g_t_h[idx] = 0.f;
    g_t_m[idx] = 0.f;
}

// Phase A: hmid = concat(s_h[i], t_h[j]) @ W_H2h + b_H2h
__global__ __launch_bounds__(256) void k_hmid(
    int d, int i_lo,
    const float* __restrict__ W_H2h, const float* __restrict__ b_H2h)
{
    const int ci = blockIdx.x;
    const int i  = i_lo + ci;
    const int j  = d - i;
    gemm64(g_s_h + (size_t)i * BH, g_t_h + (size_t)j * BH, 1024,
           W_H2h, HID, g_hmid + (size_t)ci * BH, HID, b_H2h, blockIdx.y * 64);
}

// Phase B: r = hmid@W_rec ; zs = s_x@W_kernel ; zt = t_x@W_kernel
__global__ __launch_bounds__(256) void k_zmat(
    int d, int i_lo,
    const float* __restrict__ Wk, const float* __restrict__ Wr)
{
    const int ci = blockIdx.x;
    const int i  = i_lo + ci;
    const int j  = d - i;
    const float* A;
    const float* W;
    float* C;
    if (blockIdx.z == 0)      { A = g_hmid + (size_t)ci * BH; W = Wr; C = g_r  + (size_t)ci * Z4; }
    else if (blockIdx.z == 1) { A = g_s_x  + (size_t)i  * BH; W = Wk; C = g_zs + (size_t)ci * Z4; }
    else                      { A = g_t_x  + (size_t)j  * BH; W = Wk; C = g_zt + (size_t)ci * Z4; }
    gemm64(A, A, 512, W, 4 * HID, C, 4 * HID, nullptr, blockIdx.y * 64);
}

__device__ __forceinline__ float sigmoidf(float x) { return 1.f / (1.f + __expf(-x)); }

// Phase C: gates + state update (+ final outputs)
__global__ __launch_bounds__(256) void k_gate(
    int d, int i_lo, const float* __restrict__ b_lstm, float* __restrict__ out)
{
    const int ci  = blockIdx.x;
    const int i   = i_lo + ci;
    const int j   = d - i;
    const int idx = blockIdx.y * blockDim.x + threadIdx.x;  // [0, B*H)
    const int m   = idx >> 9;
    const int h   = idx & 511;

    const size_t base = (size_t)ci * Z4 + (size_t)m * (4 * HID);
    const float bi = b_lstm[h];
    const float bf = b_lstm[HID + h];
    const float bg = b_lstm[2 * HID + h];
    const float bo = b_lstm[3 * HID + h];
    const float rI = g_r[base + h];
    const float rF = g_r[base + HID + h];
    const float rG = g_r[base + 2 * HID + h];
    const float rO = g_r[base + 3 * HID + h];

    // source-direction LSTM
    {
        const float zi = g_zs[base + h]           + rI + bi;
        const float zf = g_zs[base + HID + h]     + rF + bf;
        const float zg = g_zs[base + 2 * HID + h] + rG + bg;
        const float zo = g_zs[base + 3 * HID + h] + rO + bo;
        const size_t si = (size_t)i * BH + idx;
        const float c  = g_s_m[si];
        const float c2 = sigmoidf(zf) * c + sigmoidf(zi) * tanhf(zg);
        const float h2 = sigmoidf(zo) * tanhf(c2);
        g_s_m[si] = c2;
        g_s_h[si] = h2;
        g_s_x[si] = h2;
        if (j == T_LEN - 1) out[si] = h2;                       // source_out[i]
    }
    // target-direction LSTM
    {
        const float zi = g_zt[base + h]           + rI + bi;
        const float zf = g_zt[base + HID + h]     + rF + bf;
        const float zg = g_zt[base + 2 * HID + h] + rG + bg;
        const float zo = g_zt[base + 3 * HID + h] + rO + bo;
        const size_t ti = (size_t)j * BH + idx;
        const float c  = g_t_m[ti];
        const float c2 = sigmoidf(zf) * c + sigmoidf(zi) * tanhf(zg);
        const float h2 = sigmoidf(zo) * tanhf(c2);
        g_t_m[ti] = c2;
        g_t_h[ti] = h2;
        g_t_x[ti] = h2;
        if (i == S_LEN - 1) out[(size_t)S_LEN * BH + ti] = h2;  // t_final[0][j]
    }
}

// ---------------- launch -----------------------------------------------------
extern "C" void kernel_launch(void* const* d_in, const int* in_sizes, int n_in,
                              void* d_out, int out_size)
{
    const float* source = (const float*)d_in[0];
    const float* target = (const float*)d_in[1];
    const float* W_H2h  = (const float*)d_in[2];
    const float* b_H2h  = (const float*)d_in[3];
    const float* Wk     = (const float*)d_in[4];
    const float* Wr     = (const float*)d_in[5];
    const float* b_lstm = (const float*)d_in[6];
    float* out = (float*)d_out;

    k_init<<<(S_LEN * BH) / 256, 256>>>(source, target);

    for (int d = 0; d < S_LEN + T_LEN - 1; d++) {
        int i_lo = d - (T_LEN - 1); if (i_lo < 0) i_lo = 0;
        int i_hi = d; if (i_hi > S_LEN - 1) i_hi = S_LEN - 1;
        int nc = i_hi - i_lo + 1;
        k_hmid<<<dim3(nc, HID / 64), 256>>>(d, i_lo, W_H2h, b_H2h);
        k_zmat<<<dim3(nc, (4 * HID) / 64, 3), 256>>>(d, i_lo, Wk, Wr);
        k_gate<<<dim3(nc, BH / 256), 256>>>(d, i_lo, b_lstm, out);
    }
}